// round 6
// baseline (speedup 1.0000x reference)
#include <cuda_runtime.h>
#include <cuda_bf16.h>
#include <cstdint>

// ---------------- problem constants ----------------
#define BB 2
#define SS 2048
#define HH 1024
#define NH 16
#define NKV 4
#define HD 64
#define RG 4          // NH / NKV
#define MROWS (BB*SS) // 4096

// ---------------- scratch (device globals; no allocation allowed) ----------------
__device__ float g_q[(size_t)BB*SS*NH*HD];     // 16 MB
__device__ float g_k[(size_t)BB*SS*NKV*HD];    // 4 MB
__device__ float g_v[(size_t)BB*SS*NKV*HD];    // 4 MB
__device__ float g_att[(size_t)BB*SS*NH*HD];   // 16 MB

// ---------------- SGEMM: C[M,N] = A[M,K] @ B[K,N], all row-major fp32 ----------------
// BM=BN=64, BK=16, 256 threads, 4x4 per-thread microtile.
#define GBM 64
#define GBN 64
#define GBK 16

__global__ __launch_bounds__(256) void sgemm64(const float* __restrict__ A,
                                               const float* __restrict__ Bm,
                                               float* __restrict__ C,
                                               int M, int N, int K)
{
    __shared__ float As[GBK][GBM];
    __shared__ float Bs[GBK][GBN];

    const int tid  = threadIdx.x;
    const int row0 = blockIdx.y * GBM;
    const int col0 = blockIdx.x * GBN;

    // A tile load mapping: 64x16 floats = 256 float4 (4 per row along k)
    const int a_m = tid >> 2;        // 0..63
    const int a_k = (tid & 3) * 4;   // 0,4,8,12
    // B tile load mapping: 16x64 floats = 256 float4 (16 per row along n)
    const int b_k = tid >> 4;        // 0..15
    const int b_n = (tid & 15) * 4;  // 0..60

    const int tx = tid & 15, ty = tid >> 4;
    const int cm = ty * 4, cn = tx * 4;

    float acc[4][4];
#pragma unroll
    for (int i = 0; i < 4; i++)
#pragma unroll
        for (int j = 0; j < 4; j++) acc[i][j] = 0.f;

    for (int k0 = 0; k0 < K; k0 += GBK) {
        const float4 av = *(const float4*)(A + (size_t)(row0 + a_m) * K + k0 + a_k);
        const float4 bv = *(const float4*)(Bm + (size_t)(k0 + b_k) * N + col0 + b_n);
        __syncthreads();
        As[a_k + 0][a_m] = av.x;
        As[a_k + 1][a_m] = av.y;
        As[a_k + 2][a_m] = av.z;
        As[a_k + 3][a_m] = av.w;
        *(float4*)&Bs[b_k][b_n] = bv;
        __syncthreads();
#pragma unroll
        for (int k = 0; k < GBK; k++) {
            float ar[4], br[4];
#pragma unroll
            for (int i = 0; i < 4; i++) ar[i] = As[k][cm + i];
#pragma unroll
            for (int j = 0; j < 4; j++) br[j] = Bs[k][cn + j];
#pragma unroll
            for (int i = 0; i < 4; i++)
#pragma unroll
                for (int j = 0; j < 4; j++) acc[i][j] = fmaf(ar[i], br[j], acc[i][j]);
        }
    }

#pragma unroll
    for (int i = 0; i < 4; i++) {
        float4 o = make_float4(acc[i][0], acc[i][1], acc[i][2], acc[i][3]);
        *(float4*)(C + (size_t)(row0 + cm + i) * N + col0 + cn) = o;
    }
}

// ---------------- RoPE (in-place on (B*S*nheads, 64) layout) ----------------
__global__ void rope_kernel(float* __restrict__ x,
                            const float* __restrict__ cosb,
                            const float* __restrict__ sinb,
                            int nheads, int total)
{
    int idx = blockIdx.x * blockDim.x + threadIdx.x;
    if (idx >= total) return;                 // total = B*S*nheads*32
    const int d   = idx & 31;
    const int row = idx >> 5;                 // (b*S + s)*nheads + h
    const int s   = (row / nheads) % SS;

    const float c0 = cosb[s * HD + d],      s0 = sinb[s * HD + d];
    const float c1 = cosb[s * HD + d + 32], s1 = sinb[s * HD + d + 32];

    float* p = x + (size_t)row * HD;
    const float x0 = p[d];
    const float x1 = p[d + 32];
    p[d]      = x0 * c0 - x1 * s0;   // rotate_half lower half: -x[d+32]
    p[d + 32] = x1 * c1 + x0 * s1;   // rotate_half upper half: +x[d-32]
}

// ---------------- causal GQA flash-attention (fp32) ----------------
// grid: (S/128, NH, B); 128 threads; 1 thread = 1 query row.
#define KT 32

__global__ __launch_bounds__(128, 1) void attn_kernel(const float* __restrict__ Q,
                                                      const float* __restrict__ K,
                                                      const float* __restrict__ V,
                                                      const float* __restrict__ mask,
                                                      float* __restrict__ O)
{
    __shared__ float ks[KT][HD];
    __shared__ float vs[KT][HD];
    __shared__ float msk[KT];

    const int srow = blockIdx.x * 128 + threadIdx.x;
    const int h = blockIdx.y;
    const int b = blockIdx.z;
    const int g = h >> 2;  // h / RG

    const float* qp = Q + ((size_t)(b * SS + srow) * NH + h) * HD;
    float q[HD];
#pragma unroll
    for (int d = 0; d < HD; d += 4) {
        float4 v4 = *(const float4*)(qp + d);
        q[d] = v4.x; q[d + 1] = v4.y; q[d + 2] = v4.z; q[d + 3] = v4.w;
    }

    float acc[HD];
#pragma unroll
    for (int d = 0; d < HD; d++) acc[d] = 0.f;
    float mrow = -1e30f, lrow = 0.f;

    const int kmax = blockIdx.x * 128 + 128;   // last key any row in this block needs (+1)
    const int tid = threadIdx.x;

    for (int t0 = 0; t0 < kmax; t0 += KT) {
        __syncthreads();
        // cooperative load of KT x 64 K and V tiles (coalesced float4)
#pragma unroll
        for (int r = 0; r < 4; r++) {
            int e = tid * 4 + r * 512;        // [0, 2048)
            int j = e >> 6, d = e & 63;
            size_t gidx = ((size_t)(b * SS + t0 + j) * NKV + g) * HD + d;
            *(float4*)&ks[j][d] = *(const float4*)(K + gidx);
            *(float4*)&vs[j][d] = *(const float4*)(V + gidx);
        }
        if (tid < KT) msk[tid] = mask[b * SS + t0 + tid];
        __syncthreads();

        const int jend = min(KT, srow - t0 + 1);   // causal: keys t <= srow
        for (int j = 0; j < jend; j++) {
            float sc = 0.f;
#pragma unroll
            for (int d = 0; d < HD; d++) sc = fmaf(q[d], ks[j][d], sc);
            sc = sc * 0.125f + (1.0f - msk[j]) * -1e9f;

            if (sc > mrow) {
                const float corr = __expf(mrow - sc);
                lrow = lrow * corr + 1.0f;
#pragma unroll
                for (int d = 0; d < HD; d++) acc[d] = fmaf(acc[d], corr, vs[j][d]);
                mrow = sc;
            } else {
                const float p = __expf(sc - mrow);
                lrow += p;
#pragma unroll
                for (int d = 0; d < HD; d++) acc[d] = fmaf(p, vs[j][d], acc[d]);
            }
        }
    }

    const float inv = 1.0f / lrow;
    float* op = O + ((size_t)(b * SS + srow) * NH + h) * HD;
#pragma unroll
    for (int d = 0; d < HD; d += 4) {
        float4 o = make_float4(acc[d] * inv, acc[d + 1] * inv, acc[d + 2] * inv, acc[d + 3] * inv);
        *(float4*)(op + d) = o;
    }
}

// ---------------- launch ----------------
extern "C" void kernel_launch(void* const* d_in, const int* in_sizes, int n_in,
                              void* d_out, int out_size)
{
    const float* x    = (const float*)d_in[0];  // (B,S,H)
    const float* cosb = (const float*)d_in[1];  // (S,HD)
    const float* sinb = (const float*)d_in[2];  // (S,HD)
    const float* mask = (const float*)d_in[3];  // (B,S)
    const float* Wq   = (const float*)d_in[4];  // (H, NH*HD)
    const float* Wk   = (const float*)d_in[5];  // (H, NKV*HD)
    const float* Wv   = (const float*)d_in[6];  // (H, NKV*HD)
    const float* Wo   = (const float*)d_in[7];  // (NH*HD, H)
    float* out = (float*)d_out;                 // (B,S,H)

    float *q, *k, *v, *att;
    cudaGetSymbolAddress((void**)&q,   g_q);
    cudaGetSymbolAddress((void**)&k,   g_k);
    cudaGetSymbolAddress((void**)&v,   g_v);
    cudaGetSymbolAddress((void**)&att, g_att);

    // 1) QKV projections
    {
        dim3 gq(NH * HD / GBN, MROWS / GBM);   // (16, 64)
        sgemm64<<<gq, 256>>>(x, Wq, q, MROWS, NH * HD, HH);
        dim3 gk(NKV * HD / GBN, MROWS / GBM);  // (4, 64)
        sgemm64<<<gk, 256>>>(x, Wk, k, MROWS, NKV * HD, HH);
        sgemm64<<<gk, 256>>>(x, Wv, v, MROWS, NKV * HD, HH);
    }

    // 2) RoPE on q and k
    {
        int totq = BB * SS * NH * 32;
        rope_kernel<<<(totq + 255) / 256, 256>>>(q, cosb, sinb, NH, totq);
        int totk = BB * SS * NKV * 32;
        rope_kernel<<<(totk + 255) / 256, 256>>>(k, cosb, sinb, NKV, totk);
    }

    // 3) causal GQA attention
    {
        dim3 ga(SS / 128, NH, BB);             // (16, 16, 2)
        attn_kernel<<<ga, 128>>>(q, k, v, mask, att);
    }

    // 4) output projection
    {
        dim3 go(HH / GBN, MROWS / GBM);        // (16, 64)
        sgemm64<<<go, 256>>>(att, Wo, out, MROWS, HH, HH);
    }
}

// round 7
// speedup vs baseline: 1.0173x; 1.0173x over previous
#include <cuda_runtime.h>
#include <cuda_bf16.h>
#include <cstdint>

// ---------------- problem constants ----------------
#define BB 2
#define SS 2048
#define HH 1024
#define NH 16
#define NKV 4
#define HD 64
#define RG 4          // NH / NKV
#define MROWS (BB*SS) // 4096

// ---------------- scratch (device globals; no allocation allowed) ----------------
__device__ float g_q[(size_t)BB*SS*NH*HD];     // 16 MB
__device__ float g_k[(size_t)BB*SS*NKV*HD];    // 4 MB
__device__ float g_v[(size_t)BB*SS*NKV*HD];    // 4 MB
__device__ float g_att[(size_t)BB*SS*NH*HD];   // 16 MB

// ---------------- SGEMM: C[M,N] = A[M,K] @ B[K,N], all row-major fp32 ----------------
// BM=BN=64, BK=16, 256 threads, 4x4 per-thread microtile.
#define GBM 64
#define GBN 64
#define GBK 16

__global__ __launch_bounds__(256) void sgemm64(const float* __restrict__ A,
                                               const float* __restrict__ Bm,
                                               float* __restrict__ C,
                                               int M, int N, int K)
{
    __shared__ float As[GBK][GBM];
    __shared__ float Bs[GBK][GBN];

    const int tid  = threadIdx.x;
    const int row0 = blockIdx.y * GBM;
    const int col0 = blockIdx.x * GBN;

    // A tile load mapping: 64x16 floats = 256 float4 (4 per row along k)
    const int a_m = tid >> 2;        // 0..63
    const int a_k = (tid & 3) * 4;   // 0,4,8,12
    // B tile load mapping: 16x64 floats = 256 float4 (16 per row along n)
    const int b_k = tid >> 4;        // 0..15
    const int b_n = (tid & 15) * 4;  // 0..60

    const int tx = tid & 15, ty = tid >> 4;
    const int cm = ty * 4, cn = tx * 4;

    float acc[4][4];
#pragma unroll
    for (int i = 0; i < 4; i++)
#pragma unroll
        for (int j = 0; j < 4; j++) acc[i][j] = 0.f;

    for (int k0 = 0; k0 < K; k0 += GBK) {
        const float4 av = *(const float4*)(A + (size_t)(row0 + a_m) * K + k0 + a_k);
        const float4 bv = *(const float4*)(Bm + (size_t)(k0 + b_k) * N + col0 + b_n);
        __syncthreads();
        As[a_k + 0][a_m] = av.x;
        As[a_k + 1][a_m] = av.y;
        As[a_k + 2][a_m] = av.z;
        As[a_k + 3][a_m] = av.w;
        *(float4*)&Bs[b_k][b_n] = bv;
        __syncthreads();
#pragma unroll
        for (int k = 0; k < GBK; k++) {
            float ar[4], br[4];
#pragma unroll
            for (int i = 0; i < 4; i++) ar[i] = As[k][cm + i];
#pragma unroll
            for (int j = 0; j < 4; j++) br[j] = Bs[k][cn + j];
#pragma unroll
            for (int i = 0; i < 4; i++)
#pragma unroll
                for (int j = 0; j < 4; j++) acc[i][j] = fmaf(ar[i], br[j], acc[i][j]);
        }
    }

#pragma unroll
    for (int i = 0; i < 4; i++) {
        float4 o = make_float4(acc[i][0], acc[i][1], acc[i][2], acc[i][3]);
        *(float4*)(C + (size_t)(row0 + cm + i) * N + col0 + cn) = o;
    }
}

// ---------------- RoPE (in-place on (B*S*nheads, 64) layout) ----------------
__global__ void rope_kernel(float* __restrict__ x,
                            const float* __restrict__ cosb,
                            const float* __restrict__ sinb,
                            int nheads, int total)
{
    int idx = blockIdx.x * blockDim.x + threadIdx.x;
    if (idx >= total) return;                 // total = B*S*nheads*32
    const int d   = idx & 31;
    const int row = idx >> 5;                 // (b*S + s)*nheads + h
    const int s   = (row / nheads) % SS;

    const float c0 = cosb[s * HD + d],      s0 = sinb[s * HD + d];
    const float c1 = cosb[s * HD + d + 32], s1 = sinb[s * HD + d + 32];

    float* p = x + (size_t)row * HD;
    const float x0 = p[d];
    const float x1 = p[d + 32];
    p[d]      = x0 * c0 - x1 * s0;   // rotate_half lower half: -x[d+32]
    p[d + 32] = x1 * c1 + x0 * s1;   // rotate_half upper half: +x[d-32]
}

// ---------------- causal GQA flash-attention (fp32) ----------------
// grid: (S/128, NH, B); 128 threads; 1 thread = 1 query row.
#define KT 32

__global__ __launch_bounds__(128, 1) void attn_kernel(const float* __restrict__ Q,
                                                      const float* __restrict__ K,
                                                      const float* __restrict__ V,
                                                      const float* __restrict__ mask,
                                                      float* __restrict__ O)
{
    __shared__ float ks[KT][HD];
    __shared__ float vs[KT][HD];
    __shared__ float msk[KT];

    const int srow = blockIdx.x * 128 + threadIdx.x;
    const int h = blockIdx.y;
    const int b = blockIdx.z;
    const int g = h >> 2;  // h / RG

    const float* qp = Q + ((size_t)(b * SS + srow) * NH + h) * HD;
    float q[HD];
#pragma unroll
    for (int d = 0; d < HD; d += 4) {
        float4 v4 = *(const float4*)(qp + d);
        q[d] = v4.x; q[d + 1] = v4.y; q[d + 2] = v4.z; q[d + 3] = v4.w;
    }

    float acc[HD];
#pragma unroll
    for (int d = 0; d < HD; d++) acc[d] = 0.f;
    float mrow = -1e30f, lrow = 0.f;

    const int kmax = blockIdx.x * 128 + 128;   // last key any row in this block needs (+1)
    const int tid = threadIdx.x;

    for (int t0 = 0; t0 < kmax; t0 += KT) {
        __syncthreads();
        // cooperative load of KT x 64 K and V tiles (coalesced float4)
#pragma unroll
        for (int r = 0; r < 4; r++) {
            int e = tid * 4 + r * 512;        // [0, 2048)
            int j = e >> 6, d = e & 63;
            size_t gidx = ((size_t)(b * SS + t0 + j) * NKV + g) * HD + d;
            *(float4*)&ks[j][d] = *(const float4*)(K + gidx);
            *(float4*)&vs[j][d] = *(const float4*)(V + gidx);
        }
        if (tid < KT) msk[tid] = mask[b * SS + t0 + tid];
        __syncthreads();

        const int jend = min(KT, srow - t0 + 1);   // causal: keys t <= srow
        for (int j = 0; j < jend; j++) {
            float sc = 0.f;
#pragma unroll
            for (int d = 0; d < HD; d++) sc = fmaf(q[d], ks[j][d], sc);
            sc = sc * 0.125f + (1.0f - msk[j]) * -1e9f;

            if (sc > mrow) {
                const float corr = __expf(mrow - sc);
                lrow = lrow * corr + 1.0f;
#pragma unroll
                for (int d = 0; d < HD; d++) acc[d] = fmaf(acc[d], corr, vs[j][d]);
                mrow = sc;
            } else {
                const float p = __expf(sc - mrow);
                lrow += p;
#pragma unroll
                for (int d = 0; d < HD; d++) acc[d] = fmaf(p, vs[j][d], acc[d]);
            }
        }
    }

    const float inv = 1.0f / lrow;
    float* op = O + ((size_t)(b * SS + srow) * NH + h) * HD;
#pragma unroll
    for (int d = 0; d < HD; d += 4) {
        float4 o = make_float4(acc[d] * inv, acc[d + 1] * inv, acc[d + 2] * inv, acc[d + 3] * inv);
        *(float4*)(op + d) = o;
    }
}

// ---------------- launch ----------------
extern "C" void kernel_launch(void* const* d_in, const int* in_sizes, int n_in,
                              void* d_out, int out_size)
{
    const float* x    = (const float*)d_in[0];  // (B,S,H)
    const float* cosb = (const float*)d_in[1];  // (S,HD)
    const float* sinb = (const float*)d_in[2];  // (S,HD)
    const float* mask = (const float*)d_in[3];  // (B,S)
    const float* Wq   = (const float*)d_in[4];  // (H, NH*HD)
    const float* Wk   = (const float*)d_in[5];  // (H, NKV*HD)
    const float* Wv   = (const float*)d_in[6];  // (H, NKV*HD)
    const float* Wo   = (const float*)d_in[7];  // (NH*HD, H)
    float* out = (float*)d_out;                 // (B,S,H)

    float *q, *k, *v, *att;
    cudaGetSymbolAddress((void**)&q,   g_q);
    cudaGetSymbolAddress((void**)&k,   g_k);
    cudaGetSymbolAddress((void**)&v,   g_v);
    cudaGetSymbolAddress((void**)&att, g_att);

    // 1) QKV projections
    {
        dim3 gq(NH * HD / GBN, MROWS / GBM);   // (16, 64)
        sgemm64<<<gq, 256>>>(x, Wq, q, MROWS, NH * HD, HH);
        dim3 gk(NKV * HD / GBN, MROWS / GBM);  // (4, 64)
        sgemm64<<<gk, 256>>>(x, Wk, k, MROWS, NKV * HD, HH);
        sgemm64<<<gk, 256>>>(x, Wv, v, MROWS, NKV * HD, HH);
    }

    // 2) RoPE on q and k
    {
        int totq = BB * SS * NH * 32;
        rope_kernel<<<(totq + 255) / 256, 256>>>(q, cosb, sinb, NH, totq);
        int totk = BB * SS * NKV * 32;
        rope_kernel<<<(totk + 255) / 256, 256>>>(k, cosb, sinb, NKV, totk);
    }

    // 3) causal GQA attention
    {
        dim3 ga(SS / 128, NH, BB);             // (16, 16, 2)
        attn_kernel<<<ga, 128>>>(q, k, v, mask, att);
    }

    // 4) output projection
    {
        dim3 go(HH / GBN, MROWS / GBM);        // (16, 64)
        sgemm64<<<go, 256>>>(att, Wo, out, MROWS, HH, HH);
    }
}